// round 5
// baseline (speedup 1.0000x reference)
#include <cuda_runtime.h>

// RelativePosition: out[b, off(i) + (j-i-1)] = a[b,j] - a[b,i], for j > i.
// B=128, N=1024. Output 128 * 523776 fp32 = 268 MB -> store-BW bound.

#define B_DIM 128
#define N_DIM 1024
// triangle size per batch: N*(N-1)/2
#define TRI 523776

__global__ __launch_bounds__(256) void relpos_kernel(const float* __restrict__ a,
                                                     float* __restrict__ out) {
    const int b = blockIdx.y;
    const int i = blockIdx.x;            // 0 .. N-2 (grid.x = N-1)
    const int len = N_DIM - 1 - i;       // number of j > i

    // row offset within the triangle: sum_{r<i} (N-1-r) = i*(N-1) - i*(i-1)/2
    const long long off = (long long)i * (N_DIM - 1) - ((long long)i * (i - 1)) / 2;

    const float* arow = a + (long long)b * N_DIM;
    float* orow = out + (long long)b * TRI + off;

    const float ai = __ldg(&arow[i]);    // L1-resident broadcast

    // contiguous, coalesced stores across the row
    for (int t = threadIdx.x; t < len; t += 256) {
        orow[t] = __ldg(&arow[i + 1 + t]) - ai;
    }
}

extern "C" void kernel_launch(void* const* d_in, const int* in_sizes, int n_in,
                              void* d_out, int out_size) {
    (void)in_sizes; (void)n_in; (void)out_size;
    const float* a = (const float*)d_in[0];
    float* out = (float*)d_out;

    dim3 grid(N_DIM - 1, B_DIM);   // skip i = N-1 (empty row)
    relpos_kernel<<<grid, 256>>>(a, out);
}

// round 8
// speedup vs baseline: 1.2178x; 1.2178x over previous
#include <cuda_runtime.h>

// RelativePosition: out[b, off(i) + (j-i-1)] = a[b,j] - a[b,i], for j > i.
// B=128, N=1024. 268MB output. Row-pair balanced CTAs + float4 stores.

#define B_DIM 128
#define N_DIM 1024
#define TRI 523776            // N*(N-1)/2
#define SLOTS_PER_CTA 16      // pair-slots per CTA (512 slots total / 16 = 32 groups)
#define NTHREADS 128

// Process one output row i: writes len = N-1-i contiguous floats at off(i).
// Scalar head to 16B alignment, float4 body, scalar tail.
__device__ __forceinline__ void process_row(const float* __restrict__ arow,
                                            float* __restrict__ outb,
                                            int i, int tid)
{
    const int len  = N_DIM - 1 - i;
    const int base = i * (N_DIM - 1) - (i * (i - 1)) / 2;   // off(i)
    float* orow = outb + base;
    const float ai = __ldg(&arow[i]);

    const int head = min(len, (4 - (base & 3)) & 3);
    if (tid < head)
        orow[tid] = __ldg(&arow[i + 1 + tid]) - ai;

    const int rem  = len - head;
    const int nvec = rem >> 2;
    const int tail = rem & 3;
    const float* __restrict__ src = arow + i + 1 + head;
    float* __restrict__ dst = orow + head;                  // 16B aligned

    for (int v = tid; v < nvec; v += NTHREADS) {
        const int e = 4 * v;
        float4 w;
        w.x = __ldg(&src[e + 0]) - ai;
        w.y = __ldg(&src[e + 1]) - ai;
        w.z = __ldg(&src[e + 2]) - ai;
        w.w = __ldg(&src[e + 3]) - ai;
        *reinterpret_cast<float4*>(dst + e) = w;
    }

    if (tid < tail)
        dst[4 * nvec + tid] = __ldg(&src[4 * nvec + tid]) - ai;
}

__global__ __launch_bounds__(NTHREADS)
void relpos_kernel(const float* __restrict__ a, float* __restrict__ out)
{
    const int b   = blockIdx.y;
    const int g   = blockIdx.x;           // 0..31 pair-group
    const int tid = threadIdx.x;

    const float* __restrict__ arow = a + b * N_DIM;
    float* __restrict__ outb = out + b * TRI;

    #pragma unroll
    for (int p = 0; p < SLOTS_PER_CTA; p++) {
        const int s = g * SLOTS_PER_CTA + p;      // 0..511
        process_row(arow, outb, s, tid);          // row s, len 1023-s
        const int s2 = (N_DIM - 2) - s;           // partner row, len s+1
        if (s2 != s)                              // s==511 pairs with itself
            process_row(arow, outb, s2, tid);
    }
}

extern "C" void kernel_launch(void* const* d_in, const int* in_sizes, int n_in,
                              void* d_out, int out_size)
{
    (void)in_sizes; (void)n_in; (void)out_size;
    const float* a = (const float*)d_in[0];
    float* out = (float*)d_out;

    dim3 grid(512 / SLOTS_PER_CTA, B_DIM);   // (32, 128) = 4096 CTAs
    relpos_kernel<<<grid, NTHREADS>>>(a, out);
}

// round 9
// speedup vs baseline: 1.8486x; 1.5179x over previous
#include <cuda_runtime.h>

// RelativePosition: out[b, off(i) + (j-i-1)] = a[b,j] - a[b,i], j > i.
// B=128, N=1024, 268MB out. Pair-balanced CTAs + float4 STG + plane-transposed
// smem staging so strided reads are conflict-free single-phase LDS.

#define B_DIM 128
#define N_DIM 1024
#define TRI 523776            // N*(N-1)/2
#define SLOTS_PER_CTA 16      // 512 slots / 16 = 32 groups
#define NTHREADS 128

// smem plane layout: s[(j&3)*256 + (j>>2)] = a[j]
__device__ __forceinline__ float smem_at(const float* __restrict__ s, int j) {
    return s[((j & 3) << 8) + (j >> 2)];
}

// One output row i: len = N-1-i floats at off(i). Scalar head to 16B-align dst,
// float4 body with per-plane LDS (consecutive lanes -> consecutive banks), tail.
__device__ __forceinline__ void process_row(const float* __restrict__ s,
                                            float* __restrict__ outb,
                                            int i, int tid)
{
    const int len  = N_DIM - 1 - i;
    const int base = i * (N_DIM - 1) - (i * (i - 1)) / 2;   // off(i)
    float* orow = outb + base;
    const float ai = smem_at(s, i);

    const int head = min(len, (4 - (base & 3)) & 3);
    if (tid < head)
        orow[tid] = smem_at(s, i + 1 + tid) - ai;

    const int rem  = len - head;
    const int nvec = rem >> 2;
    const int tail = rem & 3;
    const int s0   = i + 1 + head;
    float* __restrict__ dst = orow + head;                  // 16B aligned

    // element k of vector v is a[s0 + k + 4v]:
    //   plane = (s0+k)&3 (4v doesn't change it), index = ((s0+k)>>2) + v (exact)
    const float* __restrict__ p0 = s + ((((s0 + 0) & 3) << 8) + ((s0 + 0) >> 2));
    const float* __restrict__ p1 = s + ((((s0 + 1) & 3) << 8) + ((s0 + 1) >> 2));
    const float* __restrict__ p2 = s + ((((s0 + 2) & 3) << 8) + ((s0 + 2) >> 2));
    const float* __restrict__ p3 = s + ((((s0 + 3) & 3) << 8) + ((s0 + 3) >> 2));

    for (int v = tid; v < nvec; v += NTHREADS) {
        float4 w;
        w.x = p0[v] - ai;
        w.y = p1[v] - ai;
        w.z = p2[v] - ai;
        w.w = p3[v] - ai;
        *reinterpret_cast<float4*>(dst + 4 * v) = w;
    }

    if (tid < tail)
        dst[4 * nvec + tid] = smem_at(s, s0 + 4 * nvec + tid) - ai;
}

__global__ __launch_bounds__(NTHREADS)
void relpos_kernel(const float* __restrict__ a, float* __restrict__ out)
{
    __shared__ float s[4 * 256];   // 4KB: one batch row, plane-transposed

    const int b   = blockIdx.y;
    const int g   = blockIdx.x;    // 0..31
    const int tid = threadIdx.x;

    // stage a[b][:] with LDG.128, scatter into planes (conflict-free STS)
    const float4* __restrict__ arow4 =
        reinterpret_cast<const float4*>(a + b * N_DIM);
    #pragma unroll
    for (int r = 0; r < 2; r++) {
        const int q = tid + r * NTHREADS;      // 0..255
        const float4 v = __ldg(&arow4[q]);
        s[0 * 256 + q] = v.x;
        s[1 * 256 + q] = v.y;
        s[2 * 256 + q] = v.z;
        s[3 * 256 + q] = v.w;
    }
    __syncthreads();

    float* __restrict__ outb = out + b * TRI;

    #pragma unroll 1
    for (int p = 0; p < SLOTS_PER_CTA; p++) {
        const int s1 = g * SLOTS_PER_CTA + p;  // 0..511, len 1023-s1
        process_row(s, outb, s1, tid);
        const int s2 = (N_DIM - 2) - s1;       // partner, len s1+1
        if (s2 != s1)                          // s1==511 self-pairs
            process_row(s, outb, s2, tid);
    }
}

extern "C" void kernel_launch(void* const* d_in, const int* in_sizes, int n_in,
                              void* d_out, int out_size)
{
    (void)in_sizes; (void)n_in; (void)out_size;
    const float* a = (const float*)d_in[0];
    float* out = (float*)d_out;

    dim3 grid(512 / SLOTS_PER_CTA, B_DIM);   // (32, 128) = 4096 CTAs
    relpos_kernel<<<grid, NTHREADS>>>(a, out);
}

// round 15
// speedup vs baseline: 1.9925x; 1.0779x over previous
#include <cuda_runtime.h>

// RelativePosition: out[b, off(i) + (j-i-1)] = a[b,j] - a[b,i], j > i.
// B=128, N=1024, 268MB out. Pair-balanced CTAs; 4 shifted smem copies give an
// aligned LDS.128 per float4 regardless of row phase; packed f32x2 adds.

#define B_DIM 128
#define N_DIM 1024
#define TRI 523776            // N*(N-1)/2
#define SLOTS_PER_CTA 16      // 512 slots / 16 = 32 groups
#define NTHREADS 128

__device__ __forceinline__ void sub2(float& x, float& y, float nai) {
    // (x,y) += (nai,nai) via packed add.rn.f32x2
    long long v, r, n;
    asm("mov.b64 %0, {%1, %2};" : "=l"(v) : "f"(x), "f"(y));
    asm("mov.b64 %0, {%1, %2};" : "=l"(n) : "f"(nai), "f"(nai));
    asm("add.rn.f32x2 %0, %1, %2;" : "=l"(r) : "l"(v), "l"(n));
    asm("mov.b64 {%0, %1}, %2;" : "=f"(x), "=f"(y) : "l"(r));
}

// One output row i: len = N-1-i floats at off(i).
__device__ __forceinline__ void process_row(const float* __restrict__ row,
                                            const float4 (*__restrict__ shift)[256],
                                            float* __restrict__ outb,
                                            int i, int tid)
{
    const int len  = N_DIM - 1 - i;
    const int base = i * (N_DIM - 1) - (i * (i - 1)) / 2;   // off(i)
    float* orow = outb + base;
    const float ai  = row[i];
    const float nai = -ai;

    const int head = min(len, (4 - (base & 3)) & 3);
    if (tid < head)
        orow[tid] = row[i + 1 + tid] - ai;

    const int rem  = len - head;
    const int nvec = rem >> 2;
    const int tail = rem & 3;
    const int s0   = i + 1 + head;

    const float4* __restrict__ src = &shift[s0 & 3][s0 >> 2];
    float4* __restrict__ dst = reinterpret_cast<float4*>(orow + head); // aligned

    #pragma unroll 2
    for (int v = tid; v < nvec; v += NTHREADS) {
        float4 w = src[v];                 // one aligned LDS.128
        sub2(w.x, w.y, nai);
        sub2(w.z, w.w, nai);
        dst[v] = w;                        // one STG.128
    }

    if (tid < tail)
        orow[head + 4 * nvec + tid] = row[s0 + 4 * nvec + tid] - ai;
}

__global__ __launch_bounds__(NTHREADS)
void relpos_kernel(const float* __restrict__ a, float* __restrict__ out)
{
    __shared__ float  row[1032];          // natural row + pad
    __shared__ float4 shift[4][256];      // shift[k][q] = a[4q+k .. 4q+k+3]

    const int b   = blockIdx.y;
    const int g   = blockIdx.x;           // 0..31
    const int tid = threadIdx.x;

    // stage natural row (LDG.128), zero the pad
    const float4* __restrict__ arow4 =
        reinterpret_cast<const float4*>(a + b * N_DIM);
    #pragma unroll
    for (int r = 0; r < 2; r++) {
        const int q = tid + r * NTHREADS;           // 0..255
        reinterpret_cast<float4*>(row)[q] = __ldg(&arow4[q]);
    }
    if (tid < 8) row[1024 + tid] = 0.0f;
    __syncthreads();

    // build the 4 shifted copies (one-time, ~8 iterations/thread)
    for (int idx = tid; idx < 4 * 256; idx += NTHREADS) {
        const int k = idx >> 8;
        const int q = idx & 255;
        const int p = 4 * q + k;
        shift[k][q] = make_float4(row[p], row[p + 1], row[p + 2], row[p + 3]);
    }
    __syncthreads();

    float* __restrict__ outb = out + b * TRI;

    #pragma unroll 1
    for (int p = 0; p < SLOTS_PER_CTA; p++) {
        const int s1 = g * SLOTS_PER_CTA + p;       // 0..511, len 1023-s1
        process_row(row, shift, outb, s1, tid);
        const int s2 = (N_DIM - 2) - s1;            // partner, len s1+1
        if (s2 != s1)                               // s1==511 self-pairs
            process_row(row, shift, outb, s2, tid);
    }
}

extern "C" void kernel_launch(void* const* d_in, const int* in_sizes, int n_in,
                              void* d_out, int out_size)
{
    (void)in_sizes; (void)n_in; (void)out_size;
    const float* a = (const float*)d_in[0];
    float* out = (float*)d_out;

    dim3 grid(512 / SLOTS_PER_CTA, B_DIM);   // (32, 128) = 4096 CTAs
    relpos_kernel<<<grid, NTHREADS>>>(a, out);
}